// round 6
// baseline (speedup 1.0000x reference)
#include <cuda_runtime.h>

#define N_NODES 100000
#define E_EDGES 1600000
#define NEG 0.2f
#define EPSV 1e-16f

#define SCAN_B 1024
#define SCAN_G ((N_NODES + SCAN_B - 1) / SCAN_B)   // 98

// Scratch (no allocs allowed)
__device__ int   g_cnt[N_NODES];        // in-degree histogram (real edges)
__device__ int   g_row[N_NODES + 1];    // CSR row starts
__device__ int   g_fill[N_NODES];       // scatter cursors
__device__ int   g_adj[E_EDGES];        // src ids sorted by dst
__device__ int   g_bsum[128];           // scan block sums
__device__ float g_h2[N_NODES];         // layer-2 node features
__device__ float g_S1[8];               // sum_c W1[h,c]*att_src1[h,c]
__device__ float g_D1[8];
__device__ float g_sc2[3];              // att_src2, att_dst2, b2

// ---- zero histogram + per-head logit coefficients ----------------------
__global__ void k_zero(const float* __restrict__ W1,
                       const float* __restrict__ as1,
                       const float* __restrict__ ad1,
                       const float* __restrict__ as2,
                       const float* __restrict__ ad2,
                       const float* __restrict__ b2) {
    int i = blockIdx.x * blockDim.x + threadIdx.x;
    if (i < N_NODES) g_cnt[i] = 0;
    if (blockIdx.x == 0) {
        int h = threadIdx.x;
        if (h < 8) {
            float s = 0.f, d = 0.f;
            #pragma unroll
            for (int c = 0; c < 16; c++) {
                float w = W1[h * 16 + c];
                s += w * as1[h * 16 + c];
                d += w * ad1[h * 16 + c];
            }
            g_S1[h] = s;
            g_D1[h] = d;
        }
        if (h == 8) { g_sc2[0] = as2[0]; g_sc2[1] = ad2[0]; g_sc2[2] = b2[0]; }
    }
}

// ---- in-degree histogram (real edges only; self-loops analytic) --------
__global__ void __launch_bounds__(256)
k_hist(const int* __restrict__ dst) {
    int i = blockIdx.x * blockDim.x + threadIdx.x;
    if (i < E_EDGES) atomicAdd(&g_cnt[dst[i]], 1);
}

// ---- exclusive scan: per-block (A), block sums (B), fixup (C) ----------
__global__ void k_scanA() {
    __shared__ int sh[SCAN_B];
    int t = threadIdx.x;
    int i = blockIdx.x * SCAN_B + t;
    int v = (i < N_NODES) ? g_cnt[i] : 0;
    sh[t] = v;
    __syncthreads();
    for (int off = 1; off < SCAN_B; off <<= 1) {
        int add = (t >= off) ? sh[t - off] : 0;
        __syncthreads();
        sh[t] += add;
        __syncthreads();
    }
    if (i < N_NODES) g_row[i] = sh[t] - v;           // exclusive (partial)
    if (t == SCAN_B - 1) g_bsum[blockIdx.x] = sh[t]; // block total
}

__global__ void k_scanB() {
    __shared__ int sh[128];
    int t = threadIdx.x;
    int v = (t < SCAN_G) ? g_bsum[t] : 0;
    sh[t] = v;
    __syncthreads();
    for (int off = 1; off < 128; off <<= 1) {
        int add = (t >= off) ? sh[t - off] : 0;
        __syncthreads();
        sh[t] += add;
        __syncthreads();
    }
    if (t < SCAN_G) g_bsum[t] = sh[t] - v;           // exclusive block offsets
}

__global__ void k_scanC() {
    int i = blockIdx.x * blockDim.x + threadIdx.x;
    if (i < N_NODES) {
        int r = g_row[i] + g_bsum[i / SCAN_B];
        g_row[i] = r;
        g_fill[i] = r;
    }
    if (i == 0) g_row[N_NODES] = E_EDGES;
}

// ---- counting-sort scatter: adj sorted by dst --------------------------
__global__ void __launch_bounds__(256)
k_scatter(const int* __restrict__ src, const int* __restrict__ dst) {
    int i = blockIdx.x * blockDim.x + threadIdx.x;
    if (i >= E_EDGES) return;
    int d = dst[i];
    int pos = atomicAdd(&g_fill[d], 1);
    g_adj[pos] = src[i];
}

// ---- layer-1 gather + epilogue + layer-2 projection (fused) ------------
__global__ void __launch_bounds__(128)
k_g1(const float* __restrict__ x,
     const float* __restrict__ W1, const float* __restrict__ b1,
     const float* __restrict__ W2) {
    __shared__ float sW1[128], sb1[128], sW2[128], sS[8], sD[8];
    int t = threadIdx.x;
    sW1[t] = W1[t]; sb1[t] = b1[t]; sW2[t] = W2[t];
    if (t < 8) { sS[t] = g_S1[t]; sD[t] = g_D1[t]; }
    __syncthreads();
    int n = blockIdx.x * 128 + t;
    if (n >= N_NODES) return;
    float xd = __ldg(x + n);
    float num[8], den[8], ed[8], es[8];
    #pragma unroll
    for (int h = 0; h < 8; h++) {
        es[h] = sS[h];
        ed[h] = xd * sD[h];
        float e = fmaf(xd, es[h], ed[h]);        // self loop
        e = e > 0.f ? e : NEG * e;
        float p = __expf(e);
        num[h] = p * xd;
        den[h] = p;
    }
    int beg = g_row[n], end = g_row[n + 1];
    for (int j = beg; j < end; j++) {
        float xs = __ldg(x + g_adj[j]);
        #pragma unroll
        for (int h = 0; h < 8; h++) {
            float e = fmaf(xs, es[h], ed[h]);
            e = e > 0.f ? e : NEG * e;
            float p = __expf(e);                 // no max-shift (bounded scores)
            num[h] = fmaf(p, xs, num[h]);
            den[h] += p;
        }
    }
    float acc = 0.f;
    #pragma unroll
    for (int h = 0; h < 8; h++) {
        float th = __fdividef(num[h], den[h] + EPSV);
        #pragma unroll
        for (int c = 0; c < 16; c++) {
            int k = h * 16 + c;
            float u = fmaf(th, sW1[k], sb1[k]);
            u = u > 0.f ? u : __expf(u) - 1.f;   // elu
            acc = fmaf(u, sW2[k], acc);
        }
    }
    g_h2[n] = acc;
}

// ---- layer-2 gather, fully fused with output ---------------------------
__global__ void __launch_bounds__(256)
k_g2(float* __restrict__ out) {
    int n = blockIdx.x * blockDim.x + threadIdx.x;
    if (n >= N_NODES) return;
    float a = g_sc2[0], b = g_sc2[1];
    float hd = g_h2[n];
    float hdb = hd * b;
    float e = fmaf(hd, a, hdb);                  // self loop
    e = e > 0.f ? e : NEG * e;
    float p = __expf(e);
    float num = p * hd, den = p;
    int beg = g_row[n], end = g_row[n + 1];
    for (int j = beg; j < end; j++) {
        float hs = g_h2[g_adj[j]];
        float e2 = fmaf(hs, a, hdb);
        e2 = e2 > 0.f ? e2 : NEG * e2;
        float q = __expf(e2);
        num = fmaf(q, hs, num);
        den += q;
    }
    out[n] = __fdividef(num, den + EPSV) + g_sc2[2];
}

extern "C" void kernel_launch(void* const* d_in, const int* in_sizes, int n_in,
                              void* d_out, int out_size) {
    const float* x   = (const float*)d_in[0];
    const int*   ei  = (const int*)d_in[1];   // int64 in reference -> int32 in harness
    const float* W1  = (const float*)d_in[2];
    const float* as1 = (const float*)d_in[3];
    const float* ad1 = (const float*)d_in[4];
    const float* b1  = (const float*)d_in[5];
    const float* W2  = (const float*)d_in[6];
    const float* as2 = (const float*)d_in[7];
    const float* ad2 = (const float*)d_in[8];
    const float* b2  = (const float*)d_in[9];
    float* out = (float*)d_out;

    const int* src = ei;
    const int* dst = ei + E_EDGES;

    k_zero<<<(N_NODES + 255) / 256, 256>>>(W1, as1, ad1, as2, ad2, b2);
    k_hist<<<(E_EDGES + 255) / 256, 256>>>(dst);
    k_scanA<<<SCAN_G, SCAN_B>>>();
    k_scanB<<<1, 128>>>();
    k_scanC<<<(N_NODES + 255) / 256, 256>>>();
    k_scatter<<<(E_EDGES + 255) / 256, 256>>>(src, dst);
    k_g1<<<(N_NODES + 127) / 128, 128>>>(x, W1, b1, W2);
    k_g2<<<(N_NODES + 255) / 256, 256>>>(out);
}